// round 11
// baseline (speedup 1.0000x reference)
#include <cuda_runtime.h>
#include <cstdint>

// GraphPool: out[s,a,f] = (deg(s,a)>0) * max over {a} ∪ {e in edges[s,a,:], e>=0} of atoms[s,e,f]
// S=512, A=128, F=128, D=6.  Edges arrive as int32.
//
// One CTA per s. atoms[s] tile (64KB) via cp.async.bulk (TMA); edges staged as
// int2 during TMA flight. Gather loop is BRANCHLESS: missing edges (-1) are
// clamped to the self row (fmax with self is a no-op), so each row is a
// straight-line block of 7 independent LDS.128 + a 3-deep fmax tree. deg mask
// applied as a multiply.

#define S_DIM 512
#define A_DIM 128
#define F_DIM 128
#define D_DIM 6
#define F4      (F_DIM / 4)            // 32 float4 per row
#define TILE_F4 (A_DIM * F4)           // 4096 float4 = 64KB
#define TILE_BYTES (TILE_F4 * 16)      // 65536
#define NEDGE   (A_DIM * D_DIM)        // 768 ints
#define NTHR 512
#define NWARP (NTHR / 32)              // 16 warps, 8 rows each

// smem layout: [0:8) mbarrier | [128:3200) edges | [3200:+64KB) tile
#define SM_EDGE_OFF 128
#define SM_TILE_OFF (SM_EDGE_OFF + 3072)
#define SMEM_BYTES  (SM_TILE_OFF + TILE_BYTES)   // 68736

__device__ __forceinline__ uint32_t smem_u32(const void* p) {
    uint32_t a;
    asm("{ .reg .u64 t; cvta.to.shared.u64 t, %1; cvt.u32.u64 %0, t; }" : "=r"(a) : "l"(p));
    return a;
}

__device__ __forceinline__ float4 fmax4(float4 a, float4 b) {
    return make_float4(fmaxf(a.x, b.x), fmaxf(a.y, b.y),
                       fmaxf(a.z, b.z), fmaxf(a.w, b.w));
}

__global__ __launch_bounds__(NTHR, 3)
void graphpool_kernel(const float* __restrict__ atoms,
                      const int* __restrict__ edges,
                      float* __restrict__ out) {
    extern __shared__ __align__(128) char smem[];
    uint32_t smem_base = smem_u32(smem);
    int*    esm  = reinterpret_cast<int*>(smem + SM_EDGE_OFF);
    const float4* tile = reinterpret_cast<const float4*>(smem + SM_TILE_OFF);

    const int s   = blockIdx.x;
    const int tid = threadIdx.x;
    const uint32_t mbar = smem_base;
    const uint32_t tile_sm = smem_base + SM_TILE_OFF;

    if (tid == 0) {
        asm volatile("mbarrier.init.shared.b64 [%0], 1;" :: "r"(mbar) : "memory");
    }
    __syncthreads();

    if (tid == 0) {
        asm volatile("fence.proxy.async.shared::cta;" ::: "memory");
        asm volatile("mbarrier.arrive.expect_tx.shared.b64 _, [%0], %1;"
                     :: "r"(mbar), "r"((uint32_t)TILE_BYTES) : "memory");
        const float* src = atoms + (size_t)s * (A_DIM * F_DIM);
        asm volatile(
            "cp.async.bulk.shared::cta.global.mbarrier::complete_tx::bytes "
            "[%0], [%1], %2, [%3];"
            :: "r"(tile_sm), "l"(src), "r"((uint32_t)TILE_BYTES), "r"(mbar)
            : "memory");
    }

    // Stage edges (int2) while the bulk copy is in flight.
    {
        const int2* ge2 = reinterpret_cast<const int2*>(edges + (size_t)s * NEDGE);
        int2* es2 = reinterpret_cast<int2*>(esm);
        if (tid < NEDGE / 2) es2[tid] = ge2[tid];
    }
    __syncthreads();

    // Wait for the tile (phase 0).
    {
        uint32_t done;
        asm volatile(
            "{\n\t.reg .pred p;\n\t"
            "mbarrier.try_wait.parity.acquire.cta.shared::cta.b64 p, [%1], 0;\n\t"
            "selp.b32 %0, 1, 0, p;\n\t}"
            : "=r"(done) : "r"(mbar) : "memory");
        if (!done) {
            asm volatile(
                "{\n\t.reg .pred P1;\n\t"
                "WL_%=:\n\t"
                "mbarrier.try_wait.parity.acquire.cta.shared::cta.b64 P1, [%0], 0, 0x989680;\n\t"
                "@P1 bra.uni WD_%=;\n\t"
                "bra.uni WL_%=;\n\t"
                "WD_%=:\n\t}"
                :: "r"(mbar) : "memory");
        }
    }

    const int lane = tid & 31;
    const int warp = tid >> 5;

    float4* gout = reinterpret_cast<float4*>(out) + (size_t)s * TILE_F4;

#pragma unroll 2
    for (int a = warp; a < A_DIM; a += NWARP) {
        const int2* ep = reinterpret_cast<const int2*>(&esm[a * D_DIM]);
        const int2 e01 = ep[0];
        const int2 e23 = ep[1];
        const int2 e45 = ep[2];

        // Branchless: clamp missing edges to self row (fmax no-op).
        const int i0 = (e01.x < 0) ? a : e01.x;
        const int i1 = (e01.y < 0) ? a : e01.y;
        const int i2 = (e23.x < 0) ? a : e23.x;
        const int i3 = (e23.y < 0) ? a : e23.y;
        const int i4 = (e45.x < 0) ? a : e45.x;
        const int i5 = (e45.y < 0) ? a : e45.y;

        const int deg = (e01.x >= 0) + (e01.y >= 0) + (e23.x >= 0)
                      + (e23.y >= 0) + (e45.x >= 0) + (e45.y >= 0);

        // 7 independent gathers (batched by ptxas), 3-deep fmax tree.
        const float4 gs = tile[a  * F4 + lane];
        const float4 g0 = tile[i0 * F4 + lane];
        const float4 g1 = tile[i1 * F4 + lane];
        const float4 g2 = tile[i2 * F4 + lane];
        const float4 g3 = tile[i3 * F4 + lane];
        const float4 g4 = tile[i4 * F4 + lane];
        const float4 g5 = tile[i5 * F4 + lane];

        float4 v = fmax4(fmax4(fmax4(gs, g0), fmax4(g1, g2)),
                         fmax4(fmax4(g3, g4), g5));

        const float m = (deg != 0) ? 1.0f : 0.0f;
        v.x *= m; v.y *= m; v.z *= m; v.w *= m;

        gout[a * F4 + lane] = v;               // coalesced 512B per warp
    }
}

extern "C" void kernel_launch(void* const* d_in, const int* in_sizes, int n_in,
                              void* d_out, int out_size) {
    const float* atoms = (const float*)d_in[0];
    const int*   edges = (const int*)d_in[1];
    float*       out   = (float*)d_out;

    cudaFuncSetAttribute(graphpool_kernel,
                         cudaFuncAttributeMaxDynamicSharedMemorySize, SMEM_BYTES);

    graphpool_kernel<<<S_DIM, NTHR, SMEM_BYTES>>>(atoms, edges, out);
}

// round 12
// speedup vs baseline: 1.4848x; 1.4848x over previous
#include <cuda_runtime.h>
#include <cstdint>

// GraphPool: out[s,a,f] = (deg(s,a)>0) * max over {a} ∪ {e in edges[s,a,:], e>=0} of atoms[s,e,f]
// S=512, A=128, F=128, D=6.  Edges arrive as int32.
//
// One CTA per s. atoms[s] tile (64KB) via cp.async.bulk (TMA); edges staged as
// int2 during TMA flight. Branchless gather (missing edge -> self row), 7
// independent LDS.128 batched per row, 3-deep fmax tree.
//
// R11 lesson: at 512thr the 40-reg cap spilled the 7-wide gather batch.
// This version: 256 threads, 3 CTAs/SM -> ~84 regs/thread, batch fits.

#define S_DIM 512
#define A_DIM 128
#define F_DIM 128
#define D_DIM 6
#define F4      (F_DIM / 4)            // 32 float4 per row
#define TILE_F4 (A_DIM * F4)           // 4096 float4 = 64KB
#define TILE_BYTES (TILE_F4 * 16)      // 65536
#define NEDGE   (A_DIM * D_DIM)        // 768 ints
#define NTHR 256
#define NWARP (NTHR / 32)              // 8 warps, 16 rows each

// smem layout: [0:8) mbarrier | [128:3200) edges | [3200:+64KB) tile
#define SM_EDGE_OFF 128
#define SM_TILE_OFF (SM_EDGE_OFF + 3072)
#define SMEM_BYTES  (SM_TILE_OFF + TILE_BYTES)   // 68736

__device__ __forceinline__ uint32_t smem_u32(const void* p) {
    uint32_t a;
    asm("{ .reg .u64 t; cvta.to.shared.u64 t, %1; cvt.u32.u64 %0, t; }" : "=r"(a) : "l"(p));
    return a;
}

__device__ __forceinline__ float4 fmax4(float4 a, float4 b) {
    return make_float4(fmaxf(a.x, b.x), fmaxf(a.y, b.y),
                       fmaxf(a.z, b.z), fmaxf(a.w, b.w));
}

__global__ __launch_bounds__(NTHR, 3)
void graphpool_kernel(const float* __restrict__ atoms,
                      const int* __restrict__ edges,
                      float* __restrict__ out) {
    extern __shared__ __align__(128) char smem[];
    uint32_t smem_base = smem_u32(smem);
    int*    esm  = reinterpret_cast<int*>(smem + SM_EDGE_OFF);
    const float4* tile = reinterpret_cast<const float4*>(smem + SM_TILE_OFF);

    const int s   = blockIdx.x;
    const int tid = threadIdx.x;
    const uint32_t mbar = smem_base;
    const uint32_t tile_sm = smem_base + SM_TILE_OFF;

    if (tid == 0) {
        asm volatile("mbarrier.init.shared.b64 [%0], 1;" :: "r"(mbar) : "memory");
    }
    __syncthreads();

    if (tid == 0) {
        asm volatile("fence.proxy.async.shared::cta;" ::: "memory");
        asm volatile("mbarrier.arrive.expect_tx.shared.b64 _, [%0], %1;"
                     :: "r"(mbar), "r"((uint32_t)TILE_BYTES) : "memory");
        const float* src = atoms + (size_t)s * (A_DIM * F_DIM);
        asm volatile(
            "cp.async.bulk.shared::cta.global.mbarrier::complete_tx::bytes "
            "[%0], [%1], %2, [%3];"
            :: "r"(tile_sm), "l"(src), "r"((uint32_t)TILE_BYTES), "r"(mbar)
            : "memory");
    }

    // Stage edges (int2) while the bulk copy is in flight.
    {
        const int2* ge2 = reinterpret_cast<const int2*>(edges + (size_t)s * NEDGE);
        int2* es2 = reinterpret_cast<int2*>(esm);
        if (tid < NEDGE / 2) es2[tid] = ge2[tid];
        if (tid < NEDGE / 2 - NTHR) es2[tid + NTHR] = ge2[tid + NTHR];
    }
    __syncthreads();

    // Wait for the tile (phase 0).
    {
        uint32_t done;
        asm volatile(
            "{\n\t.reg .pred p;\n\t"
            "mbarrier.try_wait.parity.acquire.cta.shared::cta.b64 p, [%1], 0;\n\t"
            "selp.b32 %0, 1, 0, p;\n\t}"
            : "=r"(done) : "r"(mbar) : "memory");
        if (!done) {
            asm volatile(
                "{\n\t.reg .pred P1;\n\t"
                "WL_%=:\n\t"
                "mbarrier.try_wait.parity.acquire.cta.shared::cta.b64 P1, [%0], 0, 0x989680;\n\t"
                "@P1 bra.uni WD_%=;\n\t"
                "bra.uni WL_%=;\n\t"
                "WD_%=:\n\t}"
                :: "r"(mbar) : "memory");
        }
    }

    const int lane = tid & 31;
    const int warp = tid >> 5;

    float4* gout = reinterpret_cast<float4*>(out) + (size_t)s * TILE_F4;

#pragma unroll 2
    for (int a = warp; a < A_DIM; a += NWARP) {
        const int2* ep = reinterpret_cast<const int2*>(&esm[a * D_DIM]);
        const int2 e01 = ep[0];
        const int2 e23 = ep[1];
        const int2 e45 = ep[2];

        // Branchless: clamp missing edges to self row (fmax no-op).
        const int i0 = (e01.x < 0) ? a : e01.x;
        const int i1 = (e01.y < 0) ? a : e01.y;
        const int i2 = (e23.x < 0) ? a : e23.x;
        const int i3 = (e23.y < 0) ? a : e23.y;
        const int i4 = (e45.x < 0) ? a : e45.x;
        const int i5 = (e45.y < 0) ? a : e45.y;

        const int deg = (e01.x >= 0) + (e01.y >= 0) + (e23.x >= 0)
                      + (e23.y >= 0) + (e45.x >= 0) + (e45.y >= 0);

        // 7 independent gathers (batched; enough regs at 256thr), fmax tree.
        const float4 gs = tile[a  * F4 + lane];
        const float4 g0 = tile[i0 * F4 + lane];
        const float4 g1 = tile[i1 * F4 + lane];
        const float4 g2 = tile[i2 * F4 + lane];
        const float4 g3 = tile[i3 * F4 + lane];
        const float4 g4 = tile[i4 * F4 + lane];
        const float4 g5 = tile[i5 * F4 + lane];

        float4 v = fmax4(fmax4(fmax4(gs, g0), fmax4(g1, g2)),
                         fmax4(fmax4(g3, g4), g5));

        const float m = (deg != 0) ? 1.0f : 0.0f;
        v.x *= m; v.y *= m; v.z *= m; v.w *= m;

        gout[a * F4 + lane] = v;               // coalesced 512B per warp
    }
}

extern "C" void kernel_launch(void* const* d_in, const int* in_sizes, int n_in,
                              void* d_out, int out_size) {
    const float* atoms = (const float*)d_in[0];
    const int*   edges = (const int*)d_in[1];
    float*       out   = (float*)d_out;

    cudaFuncSetAttribute(graphpool_kernel,
                         cudaFuncAttributeMaxDynamicSharedMemorySize, SMEM_BYTES);

    graphpool_kernel<<<S_DIM, NTHR, SMEM_BYTES>>>(atoms, edges, out);
}

// round 14
// speedup vs baseline: 1.5106x; 1.0173x over previous
#include <cuda_runtime.h>
#include <cstdint>

// GraphPool: out[s,a,f] = (deg(s,a)>0) * max over {a} ∪ {e in edges[s,a,:], e>=0} of atoms[s,e,f]
// S=512, A=128, F=128, D=6.  Edges arrive as int32.
//
// One CTA per s. atoms[s] tile (64KB) via cp.async.bulk (TMA); edges staged as
// int2 during TMA flight. Branchless gather (missing edge -> self row), 7
// independent LDS.128 batched per row, 3-deep fmax tree, deg-mask via
// max(e)<0.
//
// R12 equilibrium: 24 warps/SM + batching -> L1 only 50%. This version: 384
// threads, 3 CTAs/SM -> 36 warps/SM with reg cap 56 (batch needs ~45-50).

#define S_DIM 512
#define A_DIM 128
#define F_DIM 128
#define D_DIM 6
#define F4      (F_DIM / 4)            // 32 float4 per row
#define TILE_F4 (A_DIM * F4)           // 4096 float4 = 64KB
#define TILE_BYTES (TILE_F4 * 16)      // 65536
#define NEDGE   (A_DIM * D_DIM)        // 768 ints
#define NTHR 384
#define NWARP (NTHR / 32)              // 12 warps; rows strided

// smem layout: [0:8) mbarrier | [128:3200) edges | [3200:+64KB) tile
#define SM_EDGE_OFF 128
#define SM_TILE_OFF (SM_EDGE_OFF + 3072)
#define SMEM_BYTES  (SM_TILE_OFF + TILE_BYTES)   // 68736

__device__ __forceinline__ uint32_t smem_u32(const void* p) {
    uint32_t a;
    asm("{ .reg .u64 t; cvta.to.shared.u64 t, %1; cvt.u32.u64 %0, t; }" : "=r"(a) : "l"(p));
    return a;
}

__device__ __forceinline__ float4 fmax4(float4 a, float4 b) {
    return make_float4(fmaxf(a.x, b.x), fmaxf(a.y, b.y),
                       fmaxf(a.z, b.z), fmaxf(a.w, b.w));
}

__global__ __launch_bounds__(NTHR, 3)
void graphpool_kernel(const float* __restrict__ atoms,
                      const int* __restrict__ edges,
                      float* __restrict__ out) {
    extern __shared__ __align__(128) char smem[];
    uint32_t smem_base = smem_u32(smem);
    int*    esm  = reinterpret_cast<int*>(smem + SM_EDGE_OFF);
    const float4* tile = reinterpret_cast<const float4*>(smem + SM_TILE_OFF);

    const int s   = blockIdx.x;
    const int tid = threadIdx.x;
    const uint32_t mbar = smem_base;
    const uint32_t tile_sm = smem_base + SM_TILE_OFF;

    if (tid == 0) {
        asm volatile("mbarrier.init.shared.b64 [%0], 1;" :: "r"(mbar) : "memory");
    }
    __syncthreads();

    if (tid == 0) {
        asm volatile("fence.proxy.async.shared::cta;" ::: "memory");
        asm volatile("mbarrier.arrive.expect_tx.shared.b64 _, [%0], %1;"
                     :: "r"(mbar), "r"((uint32_t)TILE_BYTES) : "memory");
        const float* src = atoms + (size_t)s * (A_DIM * F_DIM);
        asm volatile(
            "cp.async.bulk.shared::cta.global.mbarrier::complete_tx::bytes "
            "[%0], [%1], %2, [%3];"
            :: "r"(tile_sm), "l"(src), "r"((uint32_t)TILE_BYTES), "r"(mbar)
            : "memory");
    }

    // Stage edges (int2) while the bulk copy is in flight.
    {
        const int2* ge2 = reinterpret_cast<const int2*>(edges + (size_t)s * NEDGE);
        int2* es2 = reinterpret_cast<int2*>(esm);
        if (tid < NEDGE / 2) es2[tid] = ge2[tid];
    }
    __syncthreads();

    // Wait for the tile (phase 0).
    {
        uint32_t done;
        asm volatile(
            "{\n\t.reg .pred p;\n\t"
            "mbarrier.try_wait.parity.acquire.cta.shared::cta.b64 p, [%1], 0;\n\t"
            "selp.b32 %0, 1, 0, p;\n\t}"
            : "=r"(done) : "r"(mbar) : "memory");
        if (!done) {
            asm volatile(
                "{\n\t.reg .pred P1;\n\t"
                "WL_%=:\n\t"
                "mbarrier.try_wait.parity.acquire.cta.shared::cta.b64 P1, [%0], 0, 0x989680;\n\t"
                "@P1 bra.uni WD_%=;\n\t"
                "bra.uni WL_%=;\n\t"
                "WD_%=:\n\t}"
                :: "r"(mbar) : "memory");
        }
    }

    const int lane = tid & 31;
    const int warp = tid >> 5;

    float4* gout = reinterpret_cast<float4*>(out) + (size_t)s * TILE_F4;

#pragma unroll 2
    for (int a = warp; a < A_DIM; a += NWARP) {
        const int2* ep = reinterpret_cast<const int2*>(&esm[a * D_DIM]);
        const int2 e01 = ep[0];
        const int2 e23 = ep[1];
        const int2 e45 = ep[2];

        // deg==0  <=>  all edges are -1  <=>  max(e) < 0  (only negative is -1)
        const int emax = max(max(max(e01.x, e01.y), max(e23.x, e23.y)),
                             max(e45.x, e45.y));
        const float m = (emax >= 0) ? 1.0f : 0.0f;

        // Branchless: clamp missing edges to self row (fmax no-op).
        const int i0 = (e01.x < 0) ? a : e01.x;
        const int i1 = (e01.y < 0) ? a : e01.y;
        const int i2 = (e23.x < 0) ? a : e23.x;
        const int i3 = (e23.y < 0) ? a : e23.y;
        const int i4 = (e45.x < 0) ? a : e45.x;
        const int i5 = (e45.y < 0) ? a : e45.y;

        // 7 independent gathers (batched), 3-deep fmax tree.
        const float4 gs = tile[a  * F4 + lane];
        const float4 g0 = tile[i0 * F4 + lane];
        const float4 g1 = tile[i1 * F4 + lane];
        const float4 g2 = tile[i2 * F4 + lane];
        const float4 g3 = tile[i3 * F4 + lane];
        const float4 g4 = tile[i4 * F4 + lane];
        const float4 g5 = tile[i5 * F4 + lane];

        float4 v = fmax4(fmax4(fmax4(gs, g0), fmax4(g1, g2)),
                         fmax4(fmax4(g3, g4), g5));

        v.x *= m; v.y *= m; v.z *= m; v.w *= m;

        gout[a * F4 + lane] = v;               // coalesced 512B per warp
    }
}

extern "C" void kernel_launch(void* const* d_in, const int* in_sizes, int n_in,
                              void* d_out, int out_size) {
    const float* atoms = (const float*)d_in[0];
    const int*   edges = (const int*)d_in[1];
    float*       out   = (float*)d_out;

    cudaFuncSetAttribute(graphpool_kernel,
                         cudaFuncAttributeMaxDynamicSharedMemorySize, SMEM_BYTES);

    graphpool_kernel<<<S_DIM, NTHR, SMEM_BYTES>>>(atoms, edges, out);
}